// round 13
// baseline (speedup 1.0000x reference)
#include <cuda_runtime.h>

#define CC    256        // feature dim (fixed for this problem)
#define MAXB  64         // safety headroom for num_batches
#define GRID  1184       // 148 SMs * 8 blocks, single persistent wave
#define CHUNK 32         // rows per stolen work item (32 KB of features)

// Scratch: statically initialized at module load; finalize_kernel resets
// everything after reading, so no zero pass is needed per replay.
__device__ float        g_sums[MAXB * CC];
__device__ float        g_counts[MAXB];
__device__ unsigned int g_cursor = GRID;   // next chunk to hand out

// Accumulation with dynamic work-stealing.
// 256 threads: thread t handles channels [4*(t&63), +4) of rows r0 + (t>>6) + 4k.
// The INNER LOOP BODY is byte-identical to the measured-fastest R12 version
// (dependent bidx load + branch, plain float4 deref, direct atomics) — every
// restructured body (unroll, __ldcs, smem reduction, launch_bounds(256,8))
// measured 209-241us. Only the OUTER work distribution changed: instead of a
// static 845-row share per block (which eats the full ~1.10x between-SM
// finish-time spread), blocks steal 32-row chunks from a global cursor. The
// next-chunk atomicAdd is issued before processing the current chunk, so its
// latency hides under ~6.5us of streaming.
__global__ void __launch_bounds__(256) accum_kernel(
    const float* __restrict__ feat,
    const int*   __restrict__ bidx,
    const float* __restrict__ p_ptr,
    int n)
{
    const int  c4      = (threadIdx.x & 63) * 4;
    const int  rlane   = threadIdx.x >> 6;        // 0..3 (warp-uniform)
    const bool counter = (threadIdx.x & 63) == 0; // 4 threads/block count rows

    const int nchunks = (n + CHUNK - 1) / CHUNK;

    const float p  = __ldg(p_ptr);
    const bool  p3 = (p == 3.0f);

    float a0 = 0.f, a1 = 0.f, a2 = 0.f, a3 = 0.f;
    float cnt = 0.f;
    int cur = -1;

    __shared__ int s_next;
    int chunk = blockIdx.x;                       // first chunk is implicit

    while (chunk < nchunks) {
        // prefetch the next chunk id; latency overlaps chunk processing
        if (threadIdx.x == 0)
            s_next = (int)atomicAdd(&g_cursor, 1u);

        int r0 = chunk * CHUNK;
        int r1 = r0 + CHUNK;
        if (r1 > n) r1 = n;

        #pragma unroll 1
        for (int r = r0 + rlane; r < r1; r += 4) {
            int b = __ldg(bidx + r);              // warp-uniform -> broadcast
            if (b != cur) {
                if (cur >= 0) {
                    float* s = g_sums + cur * CC + c4;
                    atomicAdd(s + 0, a0); atomicAdd(s + 1, a1);
                    atomicAdd(s + 2, a2); atomicAdd(s + 3, a3);
                    a0 = a1 = a2 = a3 = 0.f;
                    if (counter) { atomicAdd(g_counts + cur, cnt); cnt = 0.f; }
                }
                cur = b;
            }
            cnt += 1.0f;
            float4 v = *reinterpret_cast<const float4*>(feat + (size_t)r * CC + c4);
            float x0 = fmaxf(v.x, 1e-6f);
            float x1 = fmaxf(v.y, 1e-6f);
            float x2 = fmaxf(v.z, 1e-6f);
            float x3 = fmaxf(v.w, 1e-6f);
            if (p3) {  // fast path: 2 FMUL/elem, hidden under HBM traffic
                a0 += x0 * x0 * x0;
                a1 += x1 * x1 * x1;
                a2 += x2 * x2 * x2;
                a3 += x3 * x3 * x3;
            } else {   // general path (correctness for arbitrary p)
                a0 += powf(x0, p);
                a1 += powf(x1, p);
                a2 += powf(x2, p);
                a3 += powf(x3, p);
            }
        }

        __syncthreads();                          // s_next published, chunk done
        chunk = s_next;
        __syncthreads();                          // all read before next write
    }

    if (cur >= 0) {
        float* s = g_sums + cur * CC + c4;
        atomicAdd(s + 0, a0); atomicAdd(s + 1, a1);
        atomicAdd(s + 2, a2); atomicAdd(s + 3, a3);
        if (counter) atomicAdd(g_counts + cur, cnt);
    }
}

// Finalize: one block per batch row. Uses g_counts (accumulated alongside the
// sums). Re-zeroes all scratch (sums, counts, steal cursor) after reading so
// the next graph replay starts clean.
__global__ void __launch_bounds__(CC) finalize_kernel(
    const float* __restrict__ p_ptr,
    float* __restrict__ out)
{
    const int b = blockIdx.x;
    const int c = threadIdx.x;
    __shared__ float s_norm;
    __shared__ float red[CC / 32];

    const float p    = __ldg(p_ptr);
    const float cntv = g_counts[b];
    const float mean = g_sums[b * CC + c] / cntv;
    g_sums[b * CC + c] = 0.0f;                  // reset for next replay
    if (c == 0) g_counts[b] = 0.0f;
    if (b == 0 && c == 0) g_cursor = GRID;      // reset steal cursor
    const float desc = powf(mean, 1.0f / p);

    float sq = desc * desc;
    #pragma unroll
    for (int o = 16; o; o >>= 1)
        sq += __shfl_xor_sync(0xffffffffu, sq, o);
    if ((c & 31) == 0) red[c >> 5] = sq;
    __syncthreads();
    if (c == 0) {
        float t = 0.f;
        #pragma unroll
        for (int i = 0; i < CC / 32; i++) t += red[i];
        s_norm = fmaxf(sqrtf(t), 1e-12f);
    }
    __syncthreads();

    out[b * CC + c] = desc / s_norm;
}

extern "C" void kernel_launch(void* const* d_in, const int* in_sizes, int n_in,
                              void* d_out, int out_size) {
    const float* feat  = (const float*)d_in[0];
    const float* p_ptr = (const float*)d_in[1];
    const int*   bidx  = (const int*)d_in[2];

    const int n = in_sizes[2];                 // N rows
    const int C = in_sizes[0] / n;             // feature dim (== 256 here)
    int B = out_size / C;                      // num batches
    if (B < 1) B = 1;
    if (B > MAXB) B = MAXB;

    float* out = (float*)d_out;

    // 1) accumulate x^p (and row counts) into per-(batch,channel) sums,
    //    with dynamic chunk stealing to kill the between-SM finish spread.
    accum_kernel<<<GRID, 256>>>(feat, bidx, p_ptr, n);

    // 2) finalize: mean, pow(1/p), L2 normalize, reset scratch for next replay
    finalize_kernel<<<B, CC>>>(p_ptr, out);
}

// round 17
// speedup vs baseline: 6.5239x; 6.5239x over previous
#include <cuda_runtime.h>

#define CC    256        // feature dim (fixed for this problem)
#define MAXB  64         // safety headroom for num_batches
#define GRID  1184       // 148 SMs * 8 blocks, single wave (measured fastest)

// Scratch: statically zero-initialized at module load; the finalizing block
// resets everything after reading, so no zero pass is needed per replay.
__device__ float        g_sums[MAXB * CC];
__device__ float        g_counts[MAXB];
__device__ unsigned int g_done = 0;

// Accumulation: each block owns a contiguous row range [r0, r1).
// 256 threads: thread t handles channels [4*(t&63), +4) of rows r0 + (t>>6) + 4k.
// batch_idx is sorted, so per-thread the segment id changes rarely: keep a
// register accumulator and flush to global atomics (REDG) only on change/exit.
// Threads with (tid&63)==0 also count rows per segment into g_counts.
//
// FROZEN LOOP: this exact structure (dependent bidx load + branch, plain
// float4 deref, direct atomics, no min-blocks bound, static grid=1184)
// measured fastest. Variants measured and REJECTED: x16 unroll / __ldcs /
// smem cross-rlane reduction / launch_bounds(256,8) (209-241us), grid=2368
// (209us), 32-row work-stealing with in-loop barriers (1232us!). Do not
// restructure the loop or add synchronization inside it.
//
// After the grid-wide atomic handshake, the LAST block to finish runs the
// finalize (GeM mean^(1/p) + L2 normalize) in-kernel: saves the second
// kernel launch and reads g_sums while L2-hot.
__global__ void __launch_bounds__(256) accum_kernel(
    const float* __restrict__ feat,
    const int*   __restrict__ bidx,
    const float* __restrict__ p_ptr,
    int n, int rows_per_block, int B,
    float* __restrict__ out)
{
    const int  tid     = threadIdx.x;
    const int  c4      = (tid & 63) * 4;
    const int  rlane   = tid >> 6;                // 0..3 (warp-uniform)
    const bool counter = (tid & 63) == 0;         // 4 threads/block count rows
    int r0 = blockIdx.x * rows_per_block;
    int r1 = r0 + rows_per_block;
    if (r1 > n) r1 = n;

    const float p  = __ldg(p_ptr);
    const bool  p3 = (p == 3.0f);

    if (r0 < n) {
        float a0 = 0.f, a1 = 0.f, a2 = 0.f, a3 = 0.f;
        float cnt = 0.f;
        int cur = -1;

        #pragma unroll 1
        for (int r = r0 + rlane; r < r1; r += 4) {
            int b = __ldg(bidx + r);              // warp-uniform -> broadcast
            if (b != cur) {
                if (cur >= 0) {
                    float* s = g_sums + cur * CC + c4;
                    atomicAdd(s + 0, a0); atomicAdd(s + 1, a1);
                    atomicAdd(s + 2, a2); atomicAdd(s + 3, a3);
                    a0 = a1 = a2 = a3 = 0.f;
                    if (counter) { atomicAdd(g_counts + cur, cnt); cnt = 0.f; }
                }
                cur = b;
            }
            cnt += 1.0f;
            float4 v = *reinterpret_cast<const float4*>(feat + (size_t)r * CC + c4);
            float x0 = fmaxf(v.x, 1e-6f);
            float x1 = fmaxf(v.y, 1e-6f);
            float x2 = fmaxf(v.z, 1e-6f);
            float x3 = fmaxf(v.w, 1e-6f);
            if (p3) {  // fast path: 2 FMUL/elem, hidden under HBM traffic
                a0 += x0 * x0 * x0;
                a1 += x1 * x1 * x1;
                a2 += x2 * x2 * x2;
                a3 += x3 * x3 * x3;
            } else {   // general path (correctness for arbitrary p)
                a0 += powf(x0, p);
                a1 += powf(x1, p);
                a2 += powf(x2, p);
                a3 += powf(x3, p);
            }
        }
        if (cur >= 0) {
            float* s = g_sums + cur * CC + c4;
            atomicAdd(s + 0, a0); atomicAdd(s + 1, a1);
            atomicAdd(s + 2, a2); atomicAdd(s + 3, a3);
            if (counter) atomicAdd(g_counts + cur, cnt);
        }
    }

    // ---- grid-wide handshake: last block to finish runs the finalize ----
    __threadfence();                              // make this block's atomics visible
    __syncthreads();                              // all threads' atomics issued
    __shared__ unsigned int s_ticket;
    if (tid == 0) s_ticket = atomicAdd(&g_done, 1u);
    __syncthreads();
    if (s_ticket != (unsigned)(GRID - 1)) return;

    // ---- finalize (one block, 8 warps, barrier-free) ----
    // Warp w handles batches b = w, w+8, ...; lane l owns channels [8l, 8l+8).
    // L2 norm via intra-warp shuffle reduction only.
    const int wid  = tid >> 5;
    const int lane = tid & 31;
    const float ip = 1.0f / p;

    for (int b = wid; b < B; b += 8) {
        const float inv_cnt = 1.0f / g_counts[b];
        float desc[8];
        float sq = 0.f;
        #pragma unroll
        for (int j = 0; j < 8; j++) {
            int c = lane * 8 + j;
            float mean = g_sums[b * CC + c] * inv_cnt;
            g_sums[b * CC + c] = 0.0f;            // reset for next replay
            desc[j] = powf(mean, ip);
            sq += desc[j] * desc[j];
        }
        #pragma unroll
        for (int o = 16; o; o >>= 1)
            sq += __shfl_xor_sync(0xffffffffu, sq, o);
        const float inv_norm = 1.0f / fmaxf(sqrtf(sq), 1e-12f);
        #pragma unroll
        for (int j = 0; j < 8; j++)
            out[b * CC + lane * 8 + j] = desc[j] * inv_norm;
        if (lane == 0) g_counts[b] = 0.0f;        // reset for next replay
    }
    if (tid == 0) g_done = 0u;                    // reset handshake
}

extern "C" void kernel_launch(void* const* d_in, const int* in_sizes, int n_in,
                              void* d_out, int out_size) {
    const float* feat  = (const float*)d_in[0];
    const float* p_ptr = (const float*)d_in[1];
    const int*   bidx  = (const int*)d_in[2];

    const int n = in_sizes[2];                 // N rows
    const int C = in_sizes[0] / n;             // feature dim (== 256 here)
    int B = out_size / C;                      // num batches
    if (B < 1) B = 1;
    if (B > MAXB) B = MAXB;

    float* out = (float*)d_out;

    const int rpb = (n + GRID - 1) / GRID;
    accum_kernel<<<GRID, 256>>>(feat, bidx, p_ptr, n, rpb, B, out);
}